// round 6
// baseline (speedup 1.0000x reference)
#include <cuda_runtime.h>

// EpochedFutureFill == causal FIR conv, B=256, T=L=65536, via FFT of N=131072.
// Four-step decomposition: N = 256 (n1, stride 512) x 512 (n2, contiguous).
// CHUNKED: rows processed 32 at a time (K1 -> K23 -> K4 per chunk) so the 33.6MB
// per-chunk intermediate stays resident in GB300's ~126MB L2 across launches.
//   K0 : build twiddle tables
//   K1 : pack + FFT256 over n1 (strided) + w_N^{-n2 k1}  -> U[k1][n2]
//   K2f: filter row: warp-FFT512 -> Fperm (permuted per-lane layout, scaled 1/N)
//   K23: warp-autonomous FFT512 fwd + multiply + IFFT512 + w_N^{+n2 k1} (in place)
//   K4 : IFFT256 over k1 (strided) + causal unpack to y

namespace {
constexpr int N_FFT = 131072;
constexpr int T_LEN = 65536;
constexpr int PAIRS = 128;
constexpr int ROWS_F = 129;
constexpr int CHUNK = 32;  // rows per chunk (33.6 MB << L2)
constexpr float TWO_PI = 6.28318530717958647692f;
constexpr float INV_N = 1.0f / (float)N_FFT;
}

// Scratch (no cudaMalloc allowed): 135 MB intermediate + permuted filter spectrum.
__device__ float2 g_buf[(size_t)ROWS_F * N_FFT];
__device__ float2 g_fspec[N_FFT];  // Fperm[k1][q'][lane]
// Twiddle tables (forward direction: exp(-2*pi*i * ...)).
__device__ float2 g_t64[8 * 8];     // [r][t&7]  : exp(-2pi i * r*(t&7)/64)   (K1/K4)
__device__ float2 g_t256[4 * 64];   // [m][j]    : exp(-2pi i * m*j/256)      (K1/K4)
__device__ float2 g_twA[16 * 32];   // [p][t]    : exp(-2pi i * p*t/512)      (warp FFT)
__device__ float2 g_twB[32 * 16];   // [t][p]    : same, transposed           (warp FFT inv)
__device__ float2 g_w32[16];        // [j]       : exp(-2pi i * j/32)

__device__ __forceinline__ float2 cadd(float2 a, float2 b) { return make_float2(a.x + b.x, a.y + b.y); }
__device__ __forceinline__ float2 csub(float2 a, float2 b) { return make_float2(a.x - b.x, a.y - b.y); }
__device__ __forceinline__ float2 cmul(float2 a, float2 b) {
    return make_float2(fmaf(a.x, b.x, -a.y * b.y), fmaf(a.x, b.y, a.y * b.x));
}
__device__ __forceinline__ float2 cmulc(float2 a, float2 b) {  // a * conj(b)
    return make_float2(fmaf(a.x, b.x, a.y * b.y), fmaf(a.y, b.x, -a.x * b.y));
}
template <int DIR>
__device__ __forceinline__ float2 cmuli(float2 a) {  // * (i*DIR)
    return (DIR < 0) ? make_float2(a.y, -a.x) : make_float2(-a.y, a.x);
}

template <int DIR>
__device__ __forceinline__ void dft4(float2 v[4]) {
    float2 t0 = cadd(v[0], v[2]);
    float2 t1 = cadd(v[1], v[3]);
    float2 t2 = csub(v[0], v[2]);
    float2 t3 = cmuli<DIR>(csub(v[1], v[3]));
    v[0] = cadd(t0, t1);
    v[2] = csub(t0, t1);
    v[1] = cadd(t2, t3);
    v[3] = csub(t2, t3);
}

template <int DIR>
__device__ __forceinline__ void dft8(float2 v[8]) {
    const float C = 0.70710678118654752440f;
    float2 b[4], d[4];
#pragma unroll
    for (int i = 0; i < 4; i++) {
        b[i] = cadd(v[i], v[i + 4]);
        d[i] = csub(v[i], v[i + 4]);
    }
    d[1] = cmul(d[1], make_float2(C, (float)DIR * C));
    d[2] = cmuli<DIR>(d[2]);
    d[3] = cmul(d[3], make_float2(-C, (float)DIR * C));
    dft4<DIR>(b);
    dft4<DIR>(d);
    v[0] = b[0]; v[2] = b[1]; v[4] = b[2]; v[6] = b[3];
    v[1] = d[0]; v[3] = d[1]; v[5] = d[2]; v[7] = d[3];
}

// In-thread natural-order 16-pt DFT.
template <int DIR>
__device__ __forceinline__ void dft16(float2 v[16]) {
    const float C1 = 0.92387953251128674f, S1 = 0.38268343236508978f;
    const float C2 = 0.70710678118654752f;
    const float D = (float)DIR;
    float2 g[4][4];
#pragma unroll
    for (int j = 0; j < 4; j++) {
        float2 a[4] = {v[j], v[j + 4], v[j + 8], v[j + 12]};
        dft4<DIR>(a);
#pragma unroll
        for (int q = 0; q < 4; q++) g[j][q] = a[q];
    }
    float2 w1 = make_float2(C1, D * S1), w2 = make_float2(C2, D * C2);
    float2 w3 = make_float2(S1, D * C1), w6 = make_float2(-C2, D * C2);
    float2 w9 = make_float2(-C1, -D * S1);
    g[1][1] = cmul(g[1][1], w1);
    g[1][2] = cmul(g[1][2], w2);
    g[1][3] = cmul(g[1][3], w3);
    g[2][1] = cmul(g[2][1], w2);
    g[2][2] = cmuli<DIR>(g[2][2]);
    g[2][3] = cmul(g[2][3], w6);
    g[3][1] = cmul(g[3][1], w3);
    g[3][2] = cmul(g[3][2], w6);
    g[3][3] = cmul(g[3][3], w9);
#pragma unroll
    for (int q = 0; q < 4; q++) {
        float2 a[4] = {g[0][q], g[1][q], g[2][q], g[3][q]};
        dft4<DIR>(a);
#pragma unroll
        for (int s = 0; s < 4; s++) v[q + 4 * s] = a[s];
    }
}

__device__ __forceinline__ float2 shflx1(float2 a) {
    return make_float2(__shfl_xor_sync(0xffffffffu, a.x, 1),
                       __shfl_xor_sync(0xffffffffu, a.y, 1));
}

// ---------------- K0: build twiddle tables (512 threads, 1 block) ----------------
__global__ void k_init_tables() {
    int i = threadIdx.x;
    {
        int p = i >> 5, t = i & 31;
        float s, c;
        sincospif(-2.0f * (float)(p * t) / 512.0f, &s, &c);
        g_twA[p * 32 + t] = make_float2(c, s);
        g_twB[t * 16 + p] = make_float2(c, s);
    }
    if (i < 64) {
        int r = i >> 3, u = i & 7;
        float s, c;
        sincospif(-2.0f * (float)(r * u) / 64.0f, &s, &c);
        g_t64[i] = make_float2(c, s);
    }
    if (i < 256) {
        int m = i >> 6, j = i & 63;
        float s, c;
        sincospif(-2.0f * (float)(m * j) / 256.0f, &s, &c);
        g_t256[i] = make_float2(c, s);
    }
    if (i < 16) {
        float s, c;
        sincospif(-2.0f * (float)i / 32.0f, &s, &c);
        g_w32[i] = make_float2(c, s);
    }
}

// ---------------- warp-level 512-pt forward FFT ----------------
// Entry: v[r] = u[lane + 32r]. Exit: lane (p=lane>>1, h=lane&1) holds
// spectrum Y[p + 32*q' + 16*h] in v[q']. sw = 512-float2 warp-private smem.
__device__ __forceinline__ void wfft512_fwd(float2 v[16], float2* sw, int lane) {
    dft16<-1>(v);  // over r (stride-32 samples)
#pragma unroll
    for (int p = 0; p < 16; p++) v[p] = cmul(v[p], __ldg(&g_twA[p * 32 + lane]));
    int lo = lane & 15;
#pragma unroll
    for (int p = 0; p < 16; p++) sw[(lane << 4) + (p ^ lo)] = v[p];
    __syncwarp();
    int p = lane >> 1, h = lane & 1;
#pragma unroll
    for (int j = 0; j < 16; j++) v[j] = sw[((16 * h + j) << 4) + (p ^ j)];
    __syncwarp();
#pragma unroll
    for (int j = 0; j < 16; j++) {
        float2 other = shflx1(v[j]);
        if (h == 0) v[j] = cadd(v[j], other);
        else        v[j] = cmul(csub(other, v[j]), __ldg(&g_w32[j]));
    }
    dft16<-1>(v);  // over j -> q'
}

// ---------------- K2f: filter spectrum -> permuted layout, scaled 1/N ----------------
__global__ __launch_bounds__(256, 3) void k_filter_spec(const float2* __restrict__ U,
                                                        float2* __restrict__ Fp) {
    __shared__ float2 sw[8][512];
    int lane = threadIdx.x & 31, w = threadIdx.x >> 5;
    int k1 = (blockIdx.x << 3) + w;
    const float2* u = U + (size_t)PAIRS * N_FFT + (k1 << 9);
    float2 v[16];
#pragma unroll
    for (int r = 0; r < 16; r++) v[r] = u[lane + 32 * r];
    wfft512_fwd(v, sw[w], lane);
    float2* o = Fp + (k1 << 9);
#pragma unroll
    for (int q = 0; q < 16; q++)
        o[q * 32 + lane] = make_float2(v[q].x * INV_N, v[q].y * INV_N);
}

// ---------------- K23: fwd FFT512 + multiply + inv FFT512 + w_N^{+n2 k1} ----------------
__global__ __launch_bounds__(256, 3) void k_stageB_conv(float2* U, const float2* __restrict__ Fp,
                                                        int row0) {
    __shared__ float2 sw[8][512];
    int lane = threadIdx.x & 31, w = threadIdx.x >> 5;
    int k1 = (blockIdx.x << 3) + w;
    int row = row0 + blockIdx.y;
    float2* u = U + (size_t)row * N_FFT + (k1 << 9);
    float2* s = sw[w];
    float2 v[16];
#pragma unroll
    for (int r = 0; r < 16; r++) v[r] = u[lane + 32 * r];
    wfft512_fwd(v, s, lane);

    const float2* Fr = Fp + (k1 << 9);
#pragma unroll
    for (int q = 0; q < 16; q++) v[q] = cmul(v[q], __ldg(Fr + q * 32 + lane));

    // ---- inverse ----
    int p = lane >> 1, h = lane & 1;
    dft16<1>(v);
#pragma unroll
    for (int j = 0; j < 16; j++) {
        float2 other = shflx1(v[j]);
        float2 tw = __ldg(&g_w32[j]);
        if (h == 0) v[j] = cadd(v[j], cmulc(other, tw));
        else        v[j] = csub(other, cmulc(v[j], tw));
    }
#pragma unroll
    for (int j = 0; j < 16; j++) v[j] = cmulc(v[j], __ldg(&g_twB[(j + 16 * h) * 16 + p]));
    __syncwarp();
#pragma unroll
    for (int j = 0; j < 16; j++) s[((j + 16 * h) << 4) + (p ^ j)] = v[j];
    __syncwarp();
    int lo = lane & 15;
#pragma unroll
    for (int q = 0; q < 16; q++) v[q] = s[(lane << 4) + (q ^ lo)];
    dft16<1>(v);  // over p -> r  (n2 = lane + 32r)

    float sb, cb, ss, cs;
    __sincosf((TWO_PI / (float)N_FFT) * (float)(lane * k1), &sb, &cb);
    __sincosf((TWO_PI / 4096.0f) * (float)k1, &ss, &cs);  // w_N^{+32 k1}
    float2 wk = make_float2(cb, sb), wstep = make_float2(cs, ss);
#pragma unroll
    for (int r = 0; r < 16; r++) {
        u[lane + 32 * r] = cmul(v[r], wk);
        wk = cmul(wk, wstep);
    }
}

// ---------------- K1: pack + FFT256 over n1 + w_N twiddle ----------------
__global__ __launch_bounds__(512) void k_stageA(const float* __restrict__ x,
                                                const float* __restrict__ filt,
                                                float2* __restrict__ U, int row0) {
    __shared__ float2 sm[256][16];
    int tx = threadIdx.x;
    int c = tx & 15, t = tx >> 4;
    int n2 = (blockIdx.x << 4) + c;
    int row = row0 + blockIdx.y;
    float2 v[8];
    if (row < PAIRS) {
        const float* xa = x + (size_t)row * T_LEN;
        const float* xb = x + (size_t)(row + PAIRS) * T_LEN;
#pragma unroll
        for (int r = 0; r < 4; r++) {
            int n = ((t + 32 * r) << 9) + n2;
            v[r] = make_float2(__ldg(xa + n), __ldg(xb + n));
        }
    } else {
#pragma unroll
        for (int r = 0; r < 4; r++) {
            int n = ((t + 32 * r) << 9) + n2;
            v[r] = make_float2(__ldg(filt + n), 0.0f);
        }
    }
#pragma unroll
    for (int r = 4; r < 8; r++) v[r] = make_float2(0.0f, 0.0f);

    dft8<-1>(v);
#pragma unroll
    for (int r = 0; r < 8; r++) sm[8 * t + r][c] = v[r];
    __syncthreads();
#pragma unroll
    for (int r = 0; r < 8; r++) v[r] = sm[t + 32 * r][c];
    {
        int t8 = t & 7;
#pragma unroll
        for (int r = 1; r < 8; r++) v[r] = cmul(v[r], __ldg(&g_t64[r * 8 + t8]));
    }
    dft8<-1>(v);
    __syncthreads();
    {
        int base = ((t >> 3) << 6) + (t & 7);
#pragma unroll
        for (int r = 0; r < 8; r++) sm[base + 8 * r][c] = v[r];
    }
    __syncthreads();

    float s64, c64;
    __sincosf(-(TWO_PI / 2048.0f) * (float)n2, &s64, &c64);
    float2 w64 = make_float2(c64, s64);
    float2* Ur = U + (size_t)row * N_FFT;
#pragma unroll
    for (int g = 0; g < 2; g++) {
        int j = t + 32 * g;
        float2 q[4];
#pragma unroll
        for (int m = 0; m < 4; m++) q[m] = sm[j + 64 * m][c];
#pragma unroll
        for (int m = 1; m < 4; m++) q[m] = cmul(q[m], __ldg(&g_t256[m * 64 + j]));
        dft4<-1>(q);
        float sb, cb;
        __sincosf(-(TWO_PI / (float)N_FFT) * (float)(n2 * j), &sb, &cb);
        float2 wk = make_float2(cb, sb);
#pragma unroll
        for (int m = 0; m < 4; m++) {
            int k1 = j + 64 * m;
            Ur[(k1 << 9) + n2] = cmul(q[m], wk);
            wk = cmul(wk, w64);
        }
    }
}

// ---------------- K4: IFFT256 over k1 + causal unpack ----------------
__global__ __launch_bounds__(512) void k_stageAinv(const float2* __restrict__ U,
                                                   float* __restrict__ y, int row0) {
    __shared__ float2 sm[256][16];
    int tx = threadIdx.x;
    int c = tx & 15, t = tx >> 4;
    int n2 = (blockIdx.x << 4) + c;
    int row = row0 + blockIdx.y;
    const float2* u = U + (size_t)row * N_FFT + n2;
    float2 v[8];
#pragma unroll
    for (int r = 0; r < 8; r++) v[r] = __ldg(u + (size_t)((t + 32 * r) << 9));
    dft8<1>(v);
#pragma unroll
    for (int r = 0; r < 8; r++) sm[8 * t + r][c] = v[r];
    __syncthreads();
#pragma unroll
    for (int r = 0; r < 8; r++) v[r] = sm[t + 32 * r][c];
    {
        int t8 = t & 7;
#pragma unroll
        for (int r = 1; r < 8; r++) v[r] = cmulc(v[r], __ldg(&g_t64[r * 8 + t8]));
    }
    dft8<1>(v);
    __syncthreads();
    {
        int base = ((t >> 3) << 6) + (t & 7);
#pragma unroll
        for (int r = 0; r < 8; r++) sm[base + 8 * r][c] = v[r];
    }
    __syncthreads();

    float* ya = y + (size_t)row * T_LEN;
    float* yb = y + (size_t)(row + PAIRS) * T_LEN;
#pragma unroll
    for (int g = 0; g < 2; g++) {
        int j = t + 32 * g;
        float2 q[4];
#pragma unroll
        for (int m = 0; m < 4; m++) q[m] = sm[j + 64 * m][c];
#pragma unroll
        for (int m = 1; m < 4; m++) q[m] = cmulc(q[m], __ldg(&g_t256[m * 64 + j]));
        dft4<1>(q);
#pragma unroll
        for (int m = 0; m < 2; m++) {
            int n = ((j + 64 * m) << 9) + n2;
            ya[n] = q[m].x;
            yb[n] = q[m].y;
        }
    }
}

extern "C" void kernel_launch(void* const* d_in, const int* in_sizes, int n_in,
                              void* d_out, int out_size) {
    const float* x = (const float*)d_in[0];
    const float* filt = (const float*)d_in[1];
    float* y = (float*)d_out;

    float2* U = nullptr;
    float2* F = nullptr;
    cudaGetSymbolAddress((void**)&U, g_buf);
    cudaGetSymbolAddress((void**)&F, g_fspec);

    k_init_tables<<<1, 512>>>();
    // Filter row first (row 128), then its spectrum.
    k_stageA<<<dim3(32, 1), 512>>>(x, filt, U, PAIRS);
    k_filter_spec<<<32, 256>>>(U, F);

    // Chunked rows: per-chunk U (33.6 MB) stays L2-resident across K1 -> K23 -> K4.
    for (int c = 0; c < PAIRS / CHUNK; c++) {
        int r0 = c * CHUNK;
        k_stageA<<<dim3(32, CHUNK), 512>>>(x, filt, U, r0);
        k_stageB_conv<<<dim3(32, CHUNK), 256>>>(U, F, r0);
        k_stageAinv<<<dim3(32, CHUNK), 512>>>(U, y, r0);
    }
}

// round 7
// speedup vs baseline: 1.2733x; 1.2733x over previous
#include <cuda_runtime.h>

// EpochedFutureFill == causal FIR conv, B=256, T=L=65536, via FFT of N=131072.
// Four-step decomposition: N = 256 (n1, stride 512) x 512 (n2, contiguous).
//   K0 : build twiddle tables (K1/K4 only)
//   K1 : pack + FFT256 over n1 (strided) + w_N^{-n2 k1}  -> U[k1][n2]
//   K2f: filter row: warp-FFT512 -> Fperm (per-lane-contiguous layout, scaled 1/N)
//   K23: warp-autonomous FFT512 fwd + multiply + IFFT512 + w_N^{+n2 k1} (in place)
//   K4 : IFFT256 over k1 (strided) + causal unpack to y
// K23: all stage twiddles COMPUTED (2 sincosf + chained cmul) - no table loads;
// filter spectrum read as LDG.128; launch_bounds(256,4) for occupancy.

namespace {
constexpr int N_FFT = 131072;
constexpr int T_LEN = 65536;
constexpr int PAIRS = 128;
constexpr int ROWS_F = 129;
constexpr float TWO_PI = 6.28318530717958647692f;
constexpr float INV_N = 1.0f / (float)N_FFT;
// w32 = exp(-2*pi*i/32) step for chained powers
constexpr float W32C = 0.98078528040323044913f;
constexpr float W32S = -0.19509032201612826785f;
}

// Scratch (no cudaMalloc allowed): 135 MB intermediate + permuted filter spectrum.
__device__ float2 g_buf[(size_t)ROWS_F * N_FFT];
__device__ float4 g_fspec4[N_FFT / 2];  // Fperm[k1][lane][q/2], 16B-aligned
// Twiddle tables for K1/K4 (forward direction).
__device__ float2 g_t64[8 * 8];     // [r][t&7]  : exp(-2pi i * r*(t&7)/64)
__device__ float2 g_t256[4 * 64];   // [m][j]    : exp(-2pi i * m*j/256)

__device__ __forceinline__ float2 cadd(float2 a, float2 b) { return make_float2(a.x + b.x, a.y + b.y); }
__device__ __forceinline__ float2 csub(float2 a, float2 b) { return make_float2(a.x - b.x, a.y - b.y); }
__device__ __forceinline__ float2 cmul(float2 a, float2 b) {
    return make_float2(fmaf(a.x, b.x, -a.y * b.y), fmaf(a.x, b.y, a.y * b.x));
}
__device__ __forceinline__ float2 cmulc(float2 a, float2 b) {  // a * conj(b)
    return make_float2(fmaf(a.x, b.x, a.y * b.y), fmaf(a.y, b.x, -a.x * b.y));
}
template <int DIR>
__device__ __forceinline__ float2 cmuli(float2 a) {  // * (i*DIR)
    return (DIR < 0) ? make_float2(a.y, -a.x) : make_float2(-a.y, a.x);
}

template <int DIR>
__device__ __forceinline__ void dft4(float2 v[4]) {
    float2 t0 = cadd(v[0], v[2]);
    float2 t1 = cadd(v[1], v[3]);
    float2 t2 = csub(v[0], v[2]);
    float2 t3 = cmuli<DIR>(csub(v[1], v[3]));
    v[0] = cadd(t0, t1);
    v[2] = csub(t0, t1);
    v[1] = cadd(t2, t3);
    v[3] = csub(t2, t3);
}

template <int DIR>
__device__ __forceinline__ void dft8(float2 v[8]) {
    const float C = 0.70710678118654752440f;
    float2 b[4], d[4];
#pragma unroll
    for (int i = 0; i < 4; i++) {
        b[i] = cadd(v[i], v[i + 4]);
        d[i] = csub(v[i], v[i + 4]);
    }
    d[1] = cmul(d[1], make_float2(C, (float)DIR * C));
    d[2] = cmuli<DIR>(d[2]);
    d[3] = cmul(d[3], make_float2(-C, (float)DIR * C));
    dft4<DIR>(b);
    dft4<DIR>(d);
    v[0] = b[0]; v[2] = b[1]; v[4] = b[2]; v[6] = b[3];
    v[1] = d[0]; v[3] = d[1]; v[5] = d[2]; v[7] = d[3];
}

// In-thread natural-order 16-pt DFT.
template <int DIR>
__device__ __forceinline__ void dft16(float2 v[16]) {
    const float C1 = 0.92387953251128674f, S1 = 0.38268343236508978f;
    const float C2 = 0.70710678118654752f;
    const float D = (float)DIR;
    float2 g[4][4];
#pragma unroll
    for (int j = 0; j < 4; j++) {
        float2 a[4] = {v[j], v[j + 4], v[j + 8], v[j + 12]};
        dft4<DIR>(a);
#pragma unroll
        for (int q = 0; q < 4; q++) g[j][q] = a[q];
    }
    float2 w1 = make_float2(C1, D * S1), w2 = make_float2(C2, D * C2);
    float2 w3 = make_float2(S1, D * C1), w6 = make_float2(-C2, D * C2);
    float2 w9 = make_float2(-C1, -D * S1);
    g[1][1] = cmul(g[1][1], w1);
    g[1][2] = cmul(g[1][2], w2);
    g[1][3] = cmul(g[1][3], w3);
    g[2][1] = cmul(g[2][1], w2);
    g[2][2] = cmuli<DIR>(g[2][2]);
    g[2][3] = cmul(g[2][3], w6);
    g[3][1] = cmul(g[3][1], w3);
    g[3][2] = cmul(g[3][2], w6);
    g[3][3] = cmul(g[3][3], w9);
#pragma unroll
    for (int q = 0; q < 4; q++) {
        float2 a[4] = {g[0][q], g[1][q], g[2][q], g[3][q]};
        dft4<DIR>(a);
#pragma unroll
        for (int s = 0; s < 4; s++) v[q + 4 * s] = a[s];
    }
}

__device__ __forceinline__ float2 shflx1(float2 a) {
    return make_float2(__shfl_xor_sync(0xffffffffu, a.x, 1),
                       __shfl_xor_sync(0xffffffffu, a.y, 1));
}

// ---------------- K0: build twiddle tables (512 threads, 1 block) ----------------
__global__ void k_init_tables() {
    int i = threadIdx.x;
    if (i < 64) {
        int r = i >> 3, u = i & 7;
        float s, c;
        sincospif(-2.0f * (float)(r * u) / 64.0f, &s, &c);
        g_t64[i] = make_float2(c, s);
    }
    if (i < 256) {
        int m = i >> 6, j = i & 63;
        float s, c;
        sincospif(-2.0f * (float)(m * j) / 256.0f, &s, &c);
        g_t256[i] = make_float2(c, s);
    }
}

// ---------------- warp-level 512-pt forward FFT (computed twiddles) ----------------
// Entry: v[r] = u[lane + 32r]. Exit: lane (p=lane>>1, h=lane&1) holds
// spectrum Y[p + 32*q' + 16*h] in v[q']. sw = 512-float2 warp-private smem.
__device__ __forceinline__ void wfft512_fwd(float2 v[16], float2* sw, int lane) {
    dft16<-1>(v);  // over r (stride-32 samples)
    {   // v[p] *= w512^{p*lane}: chained powers of exp(-2pi i lane/512)
        float sA, cA;
        __sincosf(-(TWO_PI / 512.0f) * (float)lane, &sA, &cA);
        float2 wA = make_float2(cA, sA), wr = wA;
#pragma unroll
        for (int p = 1; p < 16; p++) { v[p] = cmul(v[p], wr); wr = cmul(wr, wA); }
    }
    int lo = lane & 15;
#pragma unroll
    for (int p = 0; p < 16; p++) sw[(lane << 4) + (p ^ lo)] = v[p];
    __syncwarp();
    int p = lane >> 1, h = lane & 1;
#pragma unroll
    for (int j = 0; j < 16; j++) v[j] = sw[((16 * h + j) << 4) + (p ^ j)];
    __syncwarp();
    {   // radix-2 butterfly over halves; w32^j by chained powers (literal step)
        float2 c32 = make_float2(1.0f, 0.0f);
        const float2 st = make_float2(W32C, W32S);
#pragma unroll
        for (int j = 0; j < 16; j++) {
            float2 other = shflx1(v[j]);
            if (h == 0) v[j] = cadd(v[j], other);
            else        v[j] = cmul(csub(other, v[j]), c32);
            c32 = cmul(c32, st);
        }
    }
    dft16<-1>(v);  // over j -> q'
}

// ---------------- K2f: filter spectrum -> per-lane-contiguous layout, scaled 1/N ----------
__global__ __launch_bounds__(256, 4) void k_filter_spec(const float2* __restrict__ U,
                                                        float2* __restrict__ Fp) {
    __shared__ float2 sw[8][512];
    int lane = threadIdx.x & 31, w = threadIdx.x >> 5;
    int k1 = (blockIdx.x << 3) + w;
    const float2* u = U + (size_t)PAIRS * N_FFT + (k1 << 9);
    float2 v[16];
#pragma unroll
    for (int r = 0; r < 16; r++) v[r] = u[lane + 32 * r];
    wfft512_fwd(v, sw[w], lane);
    // store per-lane contiguous: Fp[k1*512 + lane*16 + q]
    float2* o = Fp + (k1 << 9) + (lane << 4);
#pragma unroll
    for (int q = 0; q < 16; q++)
        o[q] = make_float2(v[q].x * INV_N, v[q].y * INV_N);
}

// ---------------- K23: fwd FFT512 + multiply + inv FFT512 + w_N^{+n2 k1} ----------------
__global__ __launch_bounds__(256, 4) void k_stageB_conv(float2* U, const float4* __restrict__ Fp4) {
    __shared__ float2 sw[8][512];
    int lane = threadIdx.x & 31, w = threadIdx.x >> 5;
    int k1 = (blockIdx.x << 3) + w;
    int row = blockIdx.y;
    float2* u = U + (size_t)row * N_FFT + (k1 << 9);
    float2* s = sw[w];
    float2 v[16];
#pragma unroll
    for (int r = 0; r < 16; r++) v[r] = u[lane + 32 * r];
    wfft512_fwd(v, s, lane);

    // multiply by filter spectrum: 8 x LDG.128 (per-lane contiguous layout)
    const float4* Fr = Fp4 + ((k1 << 9) + (lane << 4) >> 1);
#pragma unroll
    for (int q2 = 0; q2 < 8; q2++) {
        float4 f = __ldg(Fr + q2);
        v[2 * q2]     = cmul(v[2 * q2],     make_float2(f.x, f.y));
        v[2 * q2 + 1] = cmul(v[2 * q2 + 1], make_float2(f.z, f.w));
    }

    // ---- inverse ----
    int p = lane >> 1, h = lane & 1;
    dft16<1>(v);
    {   // butterfly with w32^j chain + twB chain: conj(w512^{p(j+16h)})
        float2 c32 = make_float2(1.0f, 0.0f);
        const float2 st32 = make_float2(W32C, W32S);
        float sWs, cWs, sW0, cW0;
        __sincosf(-(TWO_PI / 512.0f) * (float)p, &sWs, &cWs);   // ws = w512^p (fwd sign)
        __sincosf(-(TWO_PI / 32.0f) * (float)p, &sW0, &cW0);    // ws^16 = w32^p
        float2 ws = make_float2(cWs, sWs);
        float2 cB = h ? make_float2(cW0, sW0) : make_float2(1.0f, 0.0f);
#pragma unroll
        for (int j = 0; j < 16; j++) {
            float2 other = shflx1(v[j]);
            if (h == 0) v[j] = cadd(v[j], cmulc(other, c32));
            else        v[j] = csub(other, cmulc(v[j], c32));
            c32 = cmul(c32, st32);
            v[j] = cmulc(v[j], cB);
            cB = cmul(cB, ws);
        }
    }
    __syncwarp();
#pragma unroll
    for (int j = 0; j < 16; j++) s[((j + 16 * h) << 4) + (p ^ j)] = v[j];
    __syncwarp();
    int lo = lane & 15;
#pragma unroll
    for (int q = 0; q < 16; q++) v[q] = s[(lane << 4) + (q ^ lo)];
    dft16<1>(v);  // over p -> r  (n2 = lane + 32r)

    // outer twiddle w_N^{+n2 k1} and store
    float sb, cb, ss, cs;
    __sincosf((TWO_PI / (float)N_FFT) * (float)(lane * k1), &sb, &cb);
    __sincosf((TWO_PI / 4096.0f) * (float)k1, &ss, &cs);  // w_N^{+32 k1}
    float2 wk = make_float2(cb, sb), wstep = make_float2(cs, ss);
#pragma unroll
    for (int r = 0; r < 16; r++) {
        u[lane + 32 * r] = cmul(v[r], wk);
        wk = cmul(wk, wstep);
    }
}

// ---------------- K1: pack + FFT256 over n1 + w_N twiddle ----------------
__global__ __launch_bounds__(512) void k_stageA(const float* __restrict__ x,
                                                const float* __restrict__ filt,
                                                float2* __restrict__ U) {
    __shared__ float2 sm[256][16];
    int tx = threadIdx.x;
    int c = tx & 15, t = tx >> 4;
    int n2 = (blockIdx.x << 4) + c;
    int row = blockIdx.y;
    float2 v[8];
    if (row < PAIRS) {
        const float* xa = x + (size_t)row * T_LEN;
        const float* xb = x + (size_t)(row + PAIRS) * T_LEN;
#pragma unroll
        for (int r = 0; r < 4; r++) {
            int n = ((t + 32 * r) << 9) + n2;
            v[r] = make_float2(__ldg(xa + n), __ldg(xb + n));
        }
    } else {
#pragma unroll
        for (int r = 0; r < 4; r++) {
            int n = ((t + 32 * r) << 9) + n2;
            v[r] = make_float2(__ldg(filt + n), 0.0f);
        }
    }
#pragma unroll
    for (int r = 4; r < 8; r++) v[r] = make_float2(0.0f, 0.0f);

    dft8<-1>(v);
#pragma unroll
    for (int r = 0; r < 8; r++) sm[8 * t + r][c] = v[r];
    __syncthreads();
#pragma unroll
    for (int r = 0; r < 8; r++) v[r] = sm[t + 32 * r][c];
    {
        int t8 = t & 7;
#pragma unroll
        for (int r = 1; r < 8; r++) v[r] = cmul(v[r], __ldg(&g_t64[r * 8 + t8]));
    }
    dft8<-1>(v);
    __syncthreads();
    {
        int base = ((t >> 3) << 6) + (t & 7);
#pragma unroll
        for (int r = 0; r < 8; r++) sm[base + 8 * r][c] = v[r];
    }
    __syncthreads();

    float s64, c64;
    __sincosf(-(TWO_PI / 2048.0f) * (float)n2, &s64, &c64);
    float2 w64 = make_float2(c64, s64);
    float2* Ur = U + (size_t)row * N_FFT;
#pragma unroll
    for (int g = 0; g < 2; g++) {
        int j = t + 32 * g;
        float2 q[4];
#pragma unroll
        for (int m = 0; m < 4; m++) q[m] = sm[j + 64 * m][c];
#pragma unroll
        for (int m = 1; m < 4; m++) q[m] = cmul(q[m], __ldg(&g_t256[m * 64 + j]));
        dft4<-1>(q);
        float sb, cb;
        __sincosf(-(TWO_PI / (float)N_FFT) * (float)(n2 * j), &sb, &cb);
        float2 wk = make_float2(cb, sb);
#pragma unroll
        for (int m = 0; m < 4; m++) {
            int k1 = j + 64 * m;
            Ur[(k1 << 9) + n2] = cmul(q[m], wk);
            wk = cmul(wk, w64);
        }
    }
}

// ---------------- K4: IFFT256 over k1 + causal unpack ----------------
__global__ __launch_bounds__(512) void k_stageAinv(const float2* __restrict__ U,
                                                   float* __restrict__ y) {
    __shared__ float2 sm[256][16];
    int tx = threadIdx.x;
    int c = tx & 15, t = tx >> 4;
    int n2 = (blockIdx.x << 4) + c;
    int row = blockIdx.y;
    const float2* u = U + (size_t)row * N_FFT + n2;
    float2 v[8];
#pragma unroll
    for (int r = 0; r < 8; r++) v[r] = __ldg(u + (size_t)((t + 32 * r) << 9));
    dft8<1>(v);
#pragma unroll
    for (int r = 0; r < 8; r++) sm[8 * t + r][c] = v[r];
    __syncthreads();
#pragma unroll
    for (int r = 0; r < 8; r++) v[r] = sm[t + 32 * r][c];
    {
        int t8 = t & 7;
#pragma unroll
        for (int r = 1; r < 8; r++) v[r] = cmulc(v[r], __ldg(&g_t64[r * 8 + t8]));
    }
    dft8<1>(v);
    __syncthreads();
    {
        int base = ((t >> 3) << 6) + (t & 7);
#pragma unroll
        for (int r = 0; r < 8; r++) sm[base + 8 * r][c] = v[r];
    }
    __syncthreads();

    float* ya = y + (size_t)row * T_LEN;
    float* yb = y + (size_t)(row + PAIRS) * T_LEN;
#pragma unroll
    for (int g = 0; g < 2; g++) {
        int j = t + 32 * g;
        float2 q[4];
#pragma unroll
        for (int m = 0; m < 4; m++) q[m] = sm[j + 64 * m][c];
#pragma unroll
        for (int m = 1; m < 4; m++) q[m] = cmulc(q[m], __ldg(&g_t256[m * 64 + j]));
        dft4<1>(q);
#pragma unroll
        for (int m = 0; m < 2; m++) {
            int n = ((j + 64 * m) << 9) + n2;
            ya[n] = q[m].x;
            yb[n] = q[m].y;
        }
    }
}

extern "C" void kernel_launch(void* const* d_in, const int* in_sizes, int n_in,
                              void* d_out, int out_size) {
    const float* x = (const float*)d_in[0];
    const float* filt = (const float*)d_in[1];
    float* y = (float*)d_out;

    float2* U = nullptr;
    float4* F4 = nullptr;
    cudaGetSymbolAddress((void**)&U, g_buf);
    cudaGetSymbolAddress((void**)&F4, g_fspec4);

    k_init_tables<<<1, 512>>>();
    k_stageA<<<dim3(32, ROWS_F), 512>>>(x, filt, U);
    k_filter_spec<<<32, 256>>>(U, (float2*)F4);
    k_stageB_conv<<<dim3(32, PAIRS), 256>>>(U, F4);
    k_stageAinv<<<dim3(32, PAIRS), 512>>>(U, y);
}